// round 14
// baseline (speedup 1.0000x reference)
#include <cuda_runtime.h>

// LSTMOptimizer: per-element (N=524288) single LSTMCell step (input 4, H=128)
// + Linear(H,1) head. One warp per CONSECUTIVE element-pair; lane owns 4
// hidden columns.
//
// R13 = R9 pair structure + register software-pipeline of the h/c quads.
// R12 post-mortem: fused dual reduce serialized both epilogues -> reverted to
// per-element butterflies. New lever: the loop was load->wait->compute->store
// with zero memory in flight during compute; prefetching the NEXT pair's four
// 512B h/c loads before computing the current pair overlaps the ~600cyc DRAM
// latency with compute, with NO extra LDS (the R6 mistake).
//  - __launch_bounds__(128,6), grid 888 = 148x6: reg cap 85 >= ~80 live,
//    no spills (R8 lesson), 24 warps/SM.
//  - scalars load-at-use (cache lines shared across consecutive warps).

namespace {

constexpr int HH = 128;
constexpr int WSLOTS = 21;  // float4 slots per lane: 16 W rows + 4 bias + 1 wup

__device__ __forceinline__ float tanhx(float x) {
    float y;
    asm("tanh.approx.f32 %0, %1;" : "=f"(y) : "f"(x));
    return y;
}
__device__ __forceinline__ float sigx(float z) {
    return fmaf(0.5f, tanhx(0.5f * z), 0.5f);
}

// Generic recurrent term (h != 0): exact shuffle-broadcast h @ W_hh.T.
// Warp-uniform entry (guarded by __any_sync result). Rare path.
__device__ __noinline__ void add_recurrent(float zf[16], float4 h4,
                                           const float* __restrict__ W_hh,
                                           int colbase) {
    #pragma unroll 1
    for (int src = 0; src < 32; ++src) {
        const float b0 = __shfl_sync(0xffffffffu, h4.x, src);
        const float b1 = __shfl_sync(0xffffffffu, h4.y, src);
        const float b2 = __shfl_sync(0xffffffffu, h4.z, src);
        const float b3 = __shfl_sync(0xffffffffu, h4.w, src);
        const int kk = src << 2;
        #pragma unroll
        for (int g = 0; g < 4; ++g) {
            #pragma unroll
            for (int k = 0; k < 4; ++k) {
                const float* wr = W_hh + (size_t)(g * HH + colbase + k) * HH + kk;
                float zz = zf[g * 4 + k];
                zz = fmaf(__ldg(wr + 0), b0, zz);
                zz = fmaf(__ldg(wr + 1), b1, zz);
                zz = fmaf(__ldg(wr + 2), b2, zz);
                zz = fmaf(__ldg(wr + 3), b3, zz);
                zf[g * 4 + k] = zz;
            }
        }
    }
}

// Activations + cell/hidden update + head partial dot for one element.
__device__ __forceinline__ float finish_elem(const float zf[16], float4 c4,
                                             float4 wup, float4& hn4, float4& cn4) {
    const float cin[4] = {c4.x, c4.y, c4.z, c4.w};
    const float wuk[4] = {wup.x, wup.y, wup.z, wup.w};
    float hn[4], cn[4];
    float acc = 0.0f;
    #pragma unroll
    for (int k = 0; k < 4; ++k) {
        const float iv = sigx(zf[0 * 4 + k]);
        const float fv = sigx(zf[1 * 4 + k]);
        const float gg = tanhx(zf[2 * 4 + k]);
        const float ov = sigx(zf[3 * 4 + k]);
        const float cc = fmaf(fv, cin[k], iv * gg);
        const float hh = ov * tanhx(cc);
        cn[k] = cc;
        hn[k] = hh;
        acc = fmaf(hh, wuk[k], acc);
    }
    hn4 = make_float4(hn[0], hn[1], hn[2], hn[3]);
    cn4 = make_float4(cn[0], cn[1], cn[2], cn[3]);
    return acc;
}

__global__ void __launch_bounds__(128, 6)
lstm_opt_kernel(const float* __restrict__ param, const float* __restrict__ grad,
                const float* __restrict__ hmat,  const float* __restrict__ cmat,
                const float* __restrict__ momentum, const float* __restrict__ prevu,
                const float* __restrict__ W_ih,  const float* __restrict__ W_hh,
                const float* __restrict__ b_ih,  const float* __restrict__ b_hh,
                const float* __restrict__ W_up,  const float* __restrict__ b_up,
                float* __restrict__ out_upd, float* __restrict__ out_h,
                float* __restrict__ out_c,   float* __restrict__ out_mom,
                int N)
{
    // Per-lane table (float4 slots):
    //   [0..15]  W_ih row (4 floats) for gate-row r = (q>>2)*128 + lane*4 + (q&3)
    //   [16..19] bias sums b_ih[r]+b_hh[r] for the 16 rows (4 per slot)
    //   [20]     W_up[lane*4 .. +3]
    __shared__ float4 wtab[32 * WSLOTS];

    for (int idx = threadIdx.x; idx < 32 * WSLOTS; idx += blockDim.x) {
        const int l = idx / WSLOTS;
        const int q = idx % WSLOTS;
        float4 v;
        if (q < 16) {
            const int r = (q >> 2) * HH + l * 4 + (q & 3);
            v = *reinterpret_cast<const float4*>(W_ih + 4 * r);
        } else if (q < 20) {
            const int g = q - 16;
            const int r0 = g * HH + l * 4;
            v = make_float4(b_ih[r0 + 0] + b_hh[r0 + 0],
                            b_ih[r0 + 1] + b_hh[r0 + 1],
                            b_ih[r0 + 2] + b_hh[r0 + 2],
                            b_ih[r0 + 3] + b_hh[r0 + 3]);
        } else {
            v = *reinterpret_cast<const float4*>(W_up + l * 4);
        }
        wtab[idx] = v;
    }
    __syncthreads();

    const int lane    = threadIdx.x & 31;
    const int warp    = blockIdx.x * (blockDim.x >> 5) + (threadIdx.x >> 5);
    const int nwarp   = gridDim.x * (blockDim.x >> 5);
    const int colbase = lane << 2;
    const float4* wl  = wtab + lane * WSLOTS;

    const float4 wup = wl[20];
    const float  bup = __ldg(b_up);

    const int npairs = N >> 1;

    // ---- software pipeline: preload first pair's h/c quads ----
    int p = warp;
    float4 h4a, h4b, c4a, c4b;
    if (p < npairs) {
        const unsigned r0 = (unsigned)(2 * p) * HH + colbase;
        h4a = __ldcs(reinterpret_cast<const float4*>(hmat + r0));
        h4b = __ldcs(reinterpret_cast<const float4*>(hmat + r0 + HH));
        c4a = __ldcs(reinterpret_cast<const float4*>(cmat + r0));
        c4b = __ldcs(reinterpret_cast<const float4*>(cmat + r0 + HH));
    }

    #pragma unroll 1
    for (; p < npairs; p += nwarp) {
        const int ea = 2 * p;
        const int eb = ea + 1;
        const unsigned rowa = (unsigned)ea * HH + colbase;
        const unsigned rowb = rowa + HH;

        // ---- prefetch NEXT pair's h/c quads (overlaps this pair's compute) ----
        const int pn = p + nwarp;
        float4 nh4a, nh4b, nc4a, nc4b;
        if (pn < npairs) {
            const unsigned rn = (unsigned)(2 * pn) * HH + colbase;
            nh4a = __ldcs(reinterpret_cast<const float4*>(hmat + rn));
            nh4b = __ldcs(reinterpret_cast<const float4*>(hmat + rn + HH));
            nc4a = __ldcs(reinterpret_cast<const float4*>(cmat + rn));
            nc4b = __ldcs(reinterpret_cast<const float4*>(cmat + rn + HH));
        } else {
            nh4a = nh4b = nc4a = nc4b = make_float4(0.f, 0.f, 0.f, 0.f);
        }

        // scalar inputs (lines shared across consecutive warps -> cache hits)
        const float2 gv2 = __ldg(reinterpret_cast<const float2*>(grad + ea));
        const float2 pv2 = __ldg(reinterpret_cast<const float2*>(param + ea));
        const float2 mv2 = __ldg(reinterpret_cast<const float2*>(momentum + ea));
        const float2 uv2 = __ldg(reinterpret_cast<const float2*>(prevu + ea));

        // ---- gates: z = bs + W_ih @ x ; weights read once for both elems ----
        float za[16], zb[16];
        #pragma unroll
        for (int g = 0; g < 4; ++g) {
            const float4 bs = wl[16 + g];
            const float bsk[4] = {bs.x, bs.y, bs.z, bs.w};
            #pragma unroll
            for (int k = 0; k < 4; ++k) {
                const float4 w = wl[g * 4 + k];
                float z = bsk[k];
                z = fmaf(w.x, gv2.x, z);
                z = fmaf(w.y, pv2.x, z);
                z = fmaf(w.z, mv2.x, z);
                z = fmaf(w.w, uv2.x, z);
                za[g * 4 + k] = z;
                z = bsk[k];
                z = fmaf(w.x, gv2.y, z);
                z = fmaf(w.y, pv2.y, z);
                z = fmaf(w.z, mv2.y, z);
                z = fmaf(w.w, uv2.y, z);
                zb[g * 4 + k] = z;
            }
        }

        // ---- element A ----
        {
            const bool hz = (h4a.x != 0.0f) || (h4a.y != 0.0f) ||
                            (h4a.z != 0.0f) || (h4a.w != 0.0f);
            if (__any_sync(0xffffffffu, hz))
                add_recurrent(za, h4a, W_hh, colbase);

            float4 hn4, cn4;
            float acc = finish_elem(za, c4a, wup, hn4, cn4);
            if (out_h != nullptr) {
                __stcs(reinterpret_cast<float4*>(out_h + rowa), hn4);
                __stcs(reinterpret_cast<float4*>(out_c + rowa), cn4);
            }
            #pragma unroll
            for (int off = 16; off; off >>= 1)
                acc += __shfl_xor_sync(0xffffffffu, acc, off);
            if (lane == 0) {
                const float upd = acc + bup;
                out_upd[ea] = upd;
                if (out_mom != nullptr) out_mom[ea] = fmaf(0.9f, mv2.x, upd);
            }
        }

        // ---- element B ----
        {
            const bool hz = (h4b.x != 0.0f) || (h4b.y != 0.0f) ||
                            (h4b.z != 0.0f) || (h4b.w != 0.0f);
            if (__any_sync(0xffffffffu, hz))
                add_recurrent(zb, h4b, W_hh, colbase);

            float4 hn4, cn4;
            float acc = finish_elem(zb, c4b, wup, hn4, cn4);
            if (out_h != nullptr) {
                __stcs(reinterpret_cast<float4*>(out_h + rowb), hn4);
                __stcs(reinterpret_cast<float4*>(out_c + rowb), cn4);
            }
            #pragma unroll
            for (int off = 16; off; off >>= 1)
                acc += __shfl_xor_sync(0xffffffffu, acc, off);
            if (lane == 0) {
                const float upd = acc + bup;
                out_upd[eb] = upd;
                if (out_mom != nullptr) out_mom[eb] = fmaf(0.9f, mv2.y, upd);
            }
        }

        // rotate pipeline registers
        h4a = nh4a; h4b = nh4b; c4a = nc4a; c4b = nc4b;
    }
}

}  // namespace

extern "C" void kernel_launch(void* const* d_in, const int* in_sizes, int n_in,
                              void* d_out, int out_size) {
    const float* param = (const float*)d_in[0];
    const float* grad  = (const float*)d_in[1];
    const float* h     = (const float*)d_in[2];
    const float* c     = (const float*)d_in[3];
    const float* mom   = (const float*)d_in[4];
    const float* prevu = (const float*)d_in[5];
    const float* W_ih  = (const float*)d_in[6];
    const float* W_hh  = (const float*)d_in[7];
    const float* b_ih  = (const float*)d_in[8];
    const float* b_hh  = (const float*)d_in[9];
    const float* W_up  = (const float*)d_in[10];
    const float* b_up  = (const float*)d_in[11];

    const int N = in_sizes[0];
    float* out = (float*)d_out;

    // Output layout: concat(update, h_new, c_new, momentum_new), reference order.
    float* out_upd = out;
    float* out_h   = nullptr;
    float* out_c   = nullptr;
    float* out_mom = nullptr;
    const long long full = 2LL * N + 2LL * N * 128;
    if ((long long)out_size >= full) {
        out_h   = out + N;
        out_c   = out + N + (size_t)N * 128;
        out_mom = out + N + 2 * (size_t)N * 128;
    } else if (out_size >= 2 * N) {
        out_mom = out + N;
    }

    // 888 = 148 SMs x 6 resident blocks: 24 warps/SM, one wave, reg cap 85.
    const int threads = 128;
    const int blocks  = 888;
    lstm_opt_kernel<<<blocks, threads>>>(param, grad, h, c, mom, prevu,
                                         W_ih, W_hh, b_ih, b_hh, W_up, b_up,
                                         out_upd, out_h, out_c, out_mom, N);
}

// round 15
// speedup vs baseline: 1.6866x; 1.6866x over previous
#include <cuda_runtime.h>

// LSTMOptimizer: per-element (N=524288) single LSTMCell step (input 4, H=128)
// + Linear(H,1) head. One warp per element-pair; lane owns 4 hidden columns.
//
// R14 = R7 verbatim — the session-best kernel (249.7us).
// Exploration summary (all regressed vs R7):
//  - R6 4-elem batching: 4x weight-LDS wavefronts (L1 85%) -> 278us
//  - R8 minblocks 9 (56 regs): spill traffic through L1/L2 -> 357us
//  - R10 fp16 weights: H2F unpack doubled fma-pipe work -> 390us
//  - R12 fused dual reduction: serialized both epilogues -> 268us
//  - R13 register prefetch @24 warps: compute too short to hide DRAM,
//    fewer warps exposed MORE latency -> 429us
// R7's configuration (32 warps/SM spill-free, weights read once per pair,
// tanh.approx, streaming h/c, front-batched loads) is the measured local
// optimum of the L1TEX/regfile/occupancy trade-surface.

namespace {

constexpr int HH = 128;
constexpr int WSLOTS = 21;  // float4 slots per lane: 16 W rows + 4 bias + 1 wup

__device__ __forceinline__ float tanhx(float x) {
    float y;
    asm("tanh.approx.f32 %0, %1;" : "=f"(y) : "f"(x));
    return y;
}
__device__ __forceinline__ float sigx(float z) {
    return fmaf(0.5f, tanhx(0.5f * z), 0.5f);
}

// Generic recurrent term (h != 0): exact shuffle-broadcast h @ W_hh.T.
// Warp-uniform entry (guarded by __any_sync result). Rare path.
__device__ __noinline__ void add_recurrent(float zf[16], float4 h4,
                                           const float* __restrict__ W_hh,
                                           int colbase) {
    #pragma unroll 1
    for (int src = 0; src < 32; ++src) {
        const float b0 = __shfl_sync(0xffffffffu, h4.x, src);
        const float b1 = __shfl_sync(0xffffffffu, h4.y, src);
        const float b2 = __shfl_sync(0xffffffffu, h4.z, src);
        const float b3 = __shfl_sync(0xffffffffu, h4.w, src);
        const int kk = src << 2;
        #pragma unroll
        for (int g = 0; g < 4; ++g) {
            #pragma unroll
            for (int k = 0; k < 4; ++k) {
                const float* wr = W_hh + (size_t)(g * HH + colbase + k) * HH + kk;
                float zz = zf[g * 4 + k];
                zz = fmaf(__ldg(wr + 0), b0, zz);
                zz = fmaf(__ldg(wr + 1), b1, zz);
                zz = fmaf(__ldg(wr + 2), b2, zz);
                zz = fmaf(__ldg(wr + 3), b3, zz);
                zf[g * 4 + k] = zz;
            }
        }
    }
}

// Activations + cell/hidden update + head partial dot for one element.
__device__ __forceinline__ float finish_elem(const float zf[16], float4 c4,
                                             float4 wup, float4& hn4, float4& cn4) {
    const float cin[4] = {c4.x, c4.y, c4.z, c4.w};
    const float wuk[4] = {wup.x, wup.y, wup.z, wup.w};
    float hn[4], cn[4];
    float acc = 0.0f;
    #pragma unroll
    for (int k = 0; k < 4; ++k) {
        const float iv = sigx(zf[0 * 4 + k]);
        const float fv = sigx(zf[1 * 4 + k]);
        const float gg = tanhx(zf[2 * 4 + k]);
        const float ov = sigx(zf[3 * 4 + k]);
        const float cc = fmaf(fv, cin[k], iv * gg);
        const float hh = ov * tanhx(cc);
        cn[k] = cc;
        hn[k] = hh;
        acc = fmaf(hh, wuk[k], acc);
    }
    hn4 = make_float4(hn[0], hn[1], hn[2], hn[3]);
    cn4 = make_float4(cn[0], cn[1], cn[2], cn[3]);
    return acc;
}

__global__ void __launch_bounds__(128, 8)
lstm_opt_kernel(const float* __restrict__ param, const float* __restrict__ grad,
                const float* __restrict__ hmat,  const float* __restrict__ cmat,
                const float* __restrict__ momentum, const float* __restrict__ prevu,
                const float* __restrict__ W_ih,  const float* __restrict__ W_hh,
                const float* __restrict__ b_ih,  const float* __restrict__ b_hh,
                const float* __restrict__ W_up,  const float* __restrict__ b_up,
                float* __restrict__ out_upd, float* __restrict__ out_h,
                float* __restrict__ out_c,   float* __restrict__ out_mom,
                int N)
{
    // Per-lane table (float4 slots):
    //   [0..15]  W_ih row (4 floats) for gate-row r = (q>>2)*128 + lane*4 + (q&3)
    //   [16..19] bias sums b_ih[r]+b_hh[r] for the 16 rows (4 per slot)
    //   [20]     W_up[lane*4 .. +3]
    __shared__ float4 wtab[32 * WSLOTS];

    for (int idx = threadIdx.x; idx < 32 * WSLOTS; idx += blockDim.x) {
        const int l = idx / WSLOTS;
        const int q = idx % WSLOTS;
        float4 v;
        if (q < 16) {
            const int r = (q >> 2) * HH + l * 4 + (q & 3);
            v = *reinterpret_cast<const float4*>(W_ih + 4 * r);
        } else if (q < 20) {
            const int g = q - 16;
            const int r0 = g * HH + l * 4;
            v = make_float4(b_ih[r0 + 0] + b_hh[r0 + 0],
                            b_ih[r0 + 1] + b_hh[r0 + 1],
                            b_ih[r0 + 2] + b_hh[r0 + 2],
                            b_ih[r0 + 3] + b_hh[r0 + 3]);
        } else {
            v = *reinterpret_cast<const float4*>(W_up + l * 4);
        }
        wtab[idx] = v;
    }
    __syncthreads();

    const int lane    = threadIdx.x & 31;
    const int warp    = blockIdx.x * (blockDim.x >> 5) + (threadIdx.x >> 5);
    const int nwarp   = gridDim.x * (blockDim.x >> 5);
    const int colbase = lane << 2;
    const float4* wl  = wtab + lane * WSLOTS;

    const float4 wup = wl[20];
    const float  bup = __ldg(b_up);

    int ea = warp;
    // ---- 2-element main loop (weights read once per pair) ----
    for (; ea + nwarp < N; ea += 2 * nwarp) {
        const int eb = ea + nwarp;

        // front-batched loads: 4 independent 512B/warp loads + scalars
        const unsigned rowa = (unsigned)ea * HH + colbase;
        const float4 h4a = __ldcs(reinterpret_cast<const float4*>(hmat + rowa));
        const float4 c4a = __ldcs(reinterpret_cast<const float4*>(cmat + rowa));
        const float  gva = __ldg(grad + ea);
        const float  pva = __ldg(param + ea);
        const float  mva = __ldg(momentum + ea);
        const float  uva = __ldg(prevu + ea);

        const unsigned rowb = (unsigned)eb * HH + colbase;
        const float4 h4b = __ldcs(reinterpret_cast<const float4*>(hmat + rowb));
        const float4 c4b = __ldcs(reinterpret_cast<const float4*>(cmat + rowb));
        const float  gvb = __ldg(grad + eb);
        const float  pvb = __ldg(param + eb);
        const float  mvb = __ldg(momentum + eb);
        const float  uvb = __ldg(prevu + eb);

        // gates: z = bs + W_ih @ x ; weights read once for both elems
        float za[16], zb[16];
        #pragma unroll
        for (int g = 0; g < 4; ++g) {
            const float4 bs = wl[16 + g];
            const float bsk[4] = {bs.x, bs.y, bs.z, bs.w};
            #pragma unroll
            for (int k = 0; k < 4; ++k) {
                const float4 w = wl[g * 4 + k];
                float z = bsk[k];
                z = fmaf(w.x, gva, z);
                z = fmaf(w.y, pva, z);
                z = fmaf(w.z, mva, z);
                z = fmaf(w.w, uva, z);
                za[g * 4 + k] = z;
                z = bsk[k];
                z = fmaf(w.x, gvb, z);
                z = fmaf(w.y, pvb, z);
                z = fmaf(w.z, mvb, z);
                z = fmaf(w.w, uvb, z);
                zb[g * 4 + k] = z;
            }
        }

        // element A
        {
            const bool hz = (h4a.x != 0.0f) || (h4a.y != 0.0f) ||
                            (h4a.z != 0.0f) || (h4a.w != 0.0f);
            if (__any_sync(0xffffffffu, hz))
                add_recurrent(za, h4a, W_hh, colbase);

            float4 hn4, cn4;
            float acc = finish_elem(za, c4a, wup, hn4, cn4);
            if (out_h != nullptr) {
                __stcs(reinterpret_cast<float4*>(out_h + rowa), hn4);
                __stcs(reinterpret_cast<float4*>(out_c + rowa), cn4);
            }
            #pragma unroll
            for (int off = 16; off; off >>= 1)
                acc += __shfl_xor_sync(0xffffffffu, acc, off);
            if (lane == 0) {
                const float upd = acc + bup;
                out_upd[ea] = upd;
                if (out_mom != nullptr) out_mom[ea] = fmaf(0.9f, mva, upd);
            }
        }

        // element B
        {
            const bool hz = (h4b.x != 0.0f) || (h4b.y != 0.0f) ||
                            (h4b.z != 0.0f) || (h4b.w != 0.0f);
            if (__any_sync(0xffffffffu, hz))
                add_recurrent(zb, h4b, W_hh, colbase);

            float4 hn4, cn4;
            float acc = finish_elem(zb, c4b, wup, hn4, cn4);
            if (out_h != nullptr) {
                __stcs(reinterpret_cast<float4*>(out_h + rowb), hn4);
                __stcs(reinterpret_cast<float4*>(out_c + rowb), cn4);
            }
            #pragma unroll
            for (int off = 16; off; off >>= 1)
                acc += __shfl_xor_sync(0xffffffffu, acc, off);
            if (lane == 0) {
                const float upd = acc + bup;
                out_upd[eb] = upd;
                if (out_mom != nullptr) out_mom[eb] = fmaf(0.9f, mvb, upd);
            }
        }
    }

    // ---- per-element tail ----
    for (; ea < N; ea += nwarp) {
        const unsigned row = (unsigned)ea * HH + colbase;
        const float4 h4 = __ldcs(reinterpret_cast<const float4*>(hmat + row));
        const float4 c4 = __ldcs(reinterpret_cast<const float4*>(cmat + row));
        const float  gv = __ldg(grad + ea);
        const float  pv = __ldg(param + ea);
        const float  mv = __ldg(momentum + ea);
        const float  uv = __ldg(prevu + ea);

        float zf[16];
        #pragma unroll
        for (int g = 0; g < 4; ++g) {
            const float4 bs = wl[16 + g];
            const float bsk[4] = {bs.x, bs.y, bs.z, bs.w};
            #pragma unroll
            for (int k = 0; k < 4; ++k) {
                const float4 w = wl[g * 4 + k];
                float z = bsk[k];
                z = fmaf(w.x, gv, z);
                z = fmaf(w.y, pv, z);
                z = fmaf(w.z, mv, z);
                z = fmaf(w.w, uv, z);
                zf[g * 4 + k] = z;
            }
        }
        const bool hz = (h4.x != 0.0f) || (h4.y != 0.0f) ||
                        (h4.z != 0.0f) || (h4.w != 0.0f);
        if (__any_sync(0xffffffffu, hz))
            add_recurrent(zf, h4, W_hh, colbase);

        float4 hn4, cn4;
        float acc = finish_elem(zf, c4, wup, hn4, cn4);
        if (out_h != nullptr) {
            __stcs(reinterpret_cast<float4*>(out_h + row), hn4);
            __stcs(reinterpret_cast<float4*>(out_c + row), cn4);
        }
        #pragma unroll
        for (int off = 16; off; off >>= 1)
            acc += __shfl_xor_sync(0xffffffffu, acc, off);
        if (lane == 0) {
            const float upd = acc + bup;
            out_upd[ea] = upd;
            if (out_mom != nullptr) out_mom[ea] = fmaf(0.9f, mv, upd);
        }
    }
}

}  // namespace

extern "C" void kernel_launch(void* const* d_in, const int* in_sizes, int n_in,
                              void* d_out, int out_size) {
    const float* param = (const float*)d_in[0];
    const float* grad  = (const float*)d_in[1];
    const float* h     = (const float*)d_in[2];
    const float* c     = (const float*)d_in[3];
    const float* mom   = (const float*)d_in[4];
    const float* prevu = (const float*)d_in[5];
    const float* W_ih  = (const float*)d_in[6];
    const float* W_hh  = (const float*)d_in[7];
    const float* b_ih  = (const float*)d_in[8];
    const float* b_hh  = (const float*)d_in[9];
    const float* W_up  = (const float*)d_in[10];
    const float* b_up  = (const float*)d_in[11];

    const int N = in_sizes[0];
    float* out = (float*)d_out;

    // Output layout: concat(update, h_new, c_new, momentum_new), reference order.
    float* out_upd = out;
    float* out_h   = nullptr;
    float* out_c   = nullptr;
    float* out_mom = nullptr;
    const long long full = 2LL * N + 2LL * N * 128;
    if ((long long)out_size >= full) {
        out_h   = out + N;
        out_c   = out + N + (size_t)N * 128;
        out_mom = out + N + 2 * (size_t)N * 128;
    } else if (out_size >= 2 * N) {
        out_mom = out + N;
    }

    // 1184 = 148 SMs x 8 resident blocks: 32 warps/SM, exactly one full wave.
    const int threads = 128;
    const int blocks  = 1184;
    lstm_opt_kernel<<<blocks, threads>>>(param, grad, h, c, mom, prevu,
                                         W_ih, W_hh, b_ih, b_hh, W_up, b_up,
                                         out_upd, out_h, out_c, out_mom, N);
}

// round 16
// speedup vs baseline: 1.6917x; 1.0030x over previous
#include <cuda_runtime.h>

// LSTMOptimizer: per-element (N=524288) single LSTMCell step (input 4, H=128)
// + Linear(H,1) head. One warp per element-pair; lane owns 4 hidden columns.
//
// R15 = R7 (session best, 249.7us) + ONE change: the two elements' update-
// head reductions run as two independent 5-deep SHFL butterflies interleaved
// in a single loop (after both elements' compute+stores), overlapping their
// 26-cyc SHFL latencies (~260 -> ~140 cyc/pair) instead of serializing
// A-reduce before B-compute. Unlike R12 (which also fused halves and added
// predication, and lost), this is the isolated overlap experiment:
// no select, no extra LDS, +1-2 live regs only.
// Everything else byte-identical to R7: __launch_bounds__(128,8), grid 1184,
// SMEM fp32 weight table read once per pair, tanh.approx, __ldcs/__stcs.

namespace {

constexpr int HH = 128;
constexpr int WSLOTS = 21;  // float4 slots per lane: 16 W rows + 4 bias + 1 wup

__device__ __forceinline__ float tanhx(float x) {
    float y;
    asm("tanh.approx.f32 %0, %1;" : "=f"(y) : "f"(x));
    return y;
}
__device__ __forceinline__ float sigx(float z) {
    return fmaf(0.5f, tanhx(0.5f * z), 0.5f);
}

// Generic recurrent term (h != 0): exact shuffle-broadcast h @ W_hh.T.
// Warp-uniform entry (guarded by __any_sync result). Rare path.
__device__ __noinline__ void add_recurrent(float zf[16], float4 h4,
                                           const float* __restrict__ W_hh,
                                           int colbase) {
    #pragma unroll 1
    for (int src = 0; src < 32; ++src) {
        const float b0 = __shfl_sync(0xffffffffu, h4.x, src);
        const float b1 = __shfl_sync(0xffffffffu, h4.y, src);
        const float b2 = __shfl_sync(0xffffffffu, h4.z, src);
        const float b3 = __shfl_sync(0xffffffffu, h4.w, src);
        const int kk = src << 2;
        #pragma unroll
        for (int g = 0; g < 4; ++g) {
            #pragma unroll
            for (int k = 0; k < 4; ++k) {
                const float* wr = W_hh + (size_t)(g * HH + colbase + k) * HH + kk;
                float zz = zf[g * 4 + k];
                zz = fmaf(__ldg(wr + 0), b0, zz);
                zz = fmaf(__ldg(wr + 1), b1, zz);
                zz = fmaf(__ldg(wr + 2), b2, zz);
                zz = fmaf(__ldg(wr + 3), b3, zz);
                zf[g * 4 + k] = zz;
            }
        }
    }
}

// Activations + cell/hidden update + head partial dot for one element.
__device__ __forceinline__ float finish_elem(const float zf[16], float4 c4,
                                             float4 wup, float4& hn4, float4& cn4) {
    const float cin[4] = {c4.x, c4.y, c4.z, c4.w};
    const float wuk[4] = {wup.x, wup.y, wup.z, wup.w};
    float hn[4], cn[4];
    float acc = 0.0f;
    #pragma unroll
    for (int k = 0; k < 4; ++k) {
        const float iv = sigx(zf[0 * 4 + k]);
        const float fv = sigx(zf[1 * 4 + k]);
        const float gg = tanhx(zf[2 * 4 + k]);
        const float ov = sigx(zf[3 * 4 + k]);
        const float cc = fmaf(fv, cin[k], iv * gg);
        const float hh = ov * tanhx(cc);
        cn[k] = cc;
        hn[k] = hh;
        acc = fmaf(hh, wuk[k], acc);
    }
    hn4 = make_float4(hn[0], hn[1], hn[2], hn[3]);
    cn4 = make_float4(cn[0], cn[1], cn[2], cn[3]);
    return acc;
}

__global__ void __launch_bounds__(128, 8)
lstm_opt_kernel(const float* __restrict__ param, const float* __restrict__ grad,
                const float* __restrict__ hmat,  const float* __restrict__ cmat,
                const float* __restrict__ momentum, const float* __restrict__ prevu,
                const float* __restrict__ W_ih,  const float* __restrict__ W_hh,
                const float* __restrict__ b_ih,  const float* __restrict__ b_hh,
                const float* __restrict__ W_up,  const float* __restrict__ b_up,
                float* __restrict__ out_upd, float* __restrict__ out_h,
                float* __restrict__ out_c,   float* __restrict__ out_mom,
                int N)
{
    // Per-lane table (float4 slots):
    //   [0..15]  W_ih row (4 floats) for gate-row r = (q>>2)*128 + lane*4 + (q&3)
    //   [16..19] bias sums b_ih[r]+b_hh[r] for the 16 rows (4 per slot)
    //   [20]     W_up[lane*4 .. +3]
    __shared__ float4 wtab[32 * WSLOTS];

    for (int idx = threadIdx.x; idx < 32 * WSLOTS; idx += blockDim.x) {
        const int l = idx / WSLOTS;
        const int q = idx % WSLOTS;
        float4 v;
        if (q < 16) {
            const int r = (q >> 2) * HH + l * 4 + (q & 3);
            v = *reinterpret_cast<const float4*>(W_ih + 4 * r);
        } else if (q < 20) {
            const int g = q - 16;
            const int r0 = g * HH + l * 4;
            v = make_float4(b_ih[r0 + 0] + b_hh[r0 + 0],
                            b_ih[r0 + 1] + b_hh[r0 + 1],
                            b_ih[r0 + 2] + b_hh[r0 + 2],
                            b_ih[r0 + 3] + b_hh[r0 + 3]);
        } else {
            v = *reinterpret_cast<const float4*>(W_up + l * 4);
        }
        wtab[idx] = v;
    }
    __syncthreads();

    const int lane    = threadIdx.x & 31;
    const int warp    = blockIdx.x * (blockDim.x >> 5) + (threadIdx.x >> 5);
    const int nwarp   = gridDim.x * (blockDim.x >> 5);
    const int colbase = lane << 2;
    const float4* wl  = wtab + lane * WSLOTS;

    const float4 wup = wl[20];
    const float  bup = __ldg(b_up);

    int ea = warp;
    // ---- 2-element main loop (weights read once per pair) ----
    for (; ea + nwarp < N; ea += 2 * nwarp) {
        const int eb = ea + nwarp;

        // front-batched loads: 4 independent 512B/warp loads + scalars
        const unsigned rowa = (unsigned)ea * HH + colbase;
        const float4 h4a = __ldcs(reinterpret_cast<const float4*>(hmat + rowa));
        const float4 c4a = __ldcs(reinterpret_cast<const float4*>(cmat + rowa));
        const float  gva = __ldg(grad + ea);
        const float  pva = __ldg(param + ea);
        const float  mva = __ldg(momentum + ea);
        const float  uva = __ldg(prevu + ea);

        const unsigned rowb = (unsigned)eb * HH + colbase;
        const float4 h4b = __ldcs(reinterpret_cast<const float4*>(hmat + rowb));
        const float4 c4b = __ldcs(reinterpret_cast<const float4*>(cmat + rowb));
        const float  gvb = __ldg(grad + eb);
        const float  pvb = __ldg(param + eb);
        const float  mvb = __ldg(momentum + eb);
        const float  uvb = __ldg(prevu + eb);

        // gates: z = bs + W_ih @ x ; weights read once for both elems
        float za[16], zb[16];
        #pragma unroll
        for (int g = 0; g < 4; ++g) {
            const float4 bs = wl[16 + g];
            const float bsk[4] = {bs.x, bs.y, bs.z, bs.w};
            #pragma unroll
            for (int k = 0; k < 4; ++k) {
                const float4 w = wl[g * 4 + k];
                float z = bsk[k];
                z = fmaf(w.x, gva, z);
                z = fmaf(w.y, pva, z);
                z = fmaf(w.z, mva, z);
                z = fmaf(w.w, uva, z);
                za[g * 4 + k] = z;
                z = bsk[k];
                z = fmaf(w.x, gvb, z);
                z = fmaf(w.y, pvb, z);
                z = fmaf(w.z, mvb, z);
                z = fmaf(w.w, uvb, z);
                zb[g * 4 + k] = z;
            }
        }

        float accA, accB;

        // element A: recurrent check + activations + h/c stores
        {
            const bool hz = (h4a.x != 0.0f) || (h4a.y != 0.0f) ||
                            (h4a.z != 0.0f) || (h4a.w != 0.0f);
            if (__any_sync(0xffffffffu, hz))
                add_recurrent(za, h4a, W_hh, colbase);

            float4 hn4, cn4;
            accA = finish_elem(za, c4a, wup, hn4, cn4);
            if (out_h != nullptr) {
                __stcs(reinterpret_cast<float4*>(out_h + rowa), hn4);
                __stcs(reinterpret_cast<float4*>(out_c + rowa), cn4);
            }
        }

        // element B: recurrent check + activations + h/c stores
        {
            const bool hz = (h4b.x != 0.0f) || (h4b.y != 0.0f) ||
                            (h4b.z != 0.0f) || (h4b.w != 0.0f);
            if (__any_sync(0xffffffffu, hz))
                add_recurrent(zb, h4b, W_hh, colbase);

            float4 hn4, cn4;
            accB = finish_elem(zb, c4b, wup, hn4, cn4);
            if (out_h != nullptr) {
                __stcs(reinterpret_cast<float4*>(out_h + rowb), hn4);
                __stcs(reinterpret_cast<float4*>(out_c + rowb), cn4);
            }
        }

        // two independent butterflies, interleaved: SHFL latencies overlap
        #pragma unroll
        for (int off = 16; off; off >>= 1) {
            accA += __shfl_xor_sync(0xffffffffu, accA, off);
            accB += __shfl_xor_sync(0xffffffffu, accB, off);
        }

        if (lane == 0) {
            const float updA = accA + bup;
            const float updB = accB + bup;
            out_upd[ea] = updA;
            out_upd[eb] = updB;
            if (out_mom != nullptr) {
                out_mom[ea] = fmaf(0.9f, mva, updA);
                out_mom[eb] = fmaf(0.9f, mvb, updB);
            }
        }
    }

    // ---- per-element tail ----
    for (; ea < N; ea += nwarp) {
        const unsigned row = (unsigned)ea * HH + colbase;
        const float4 h4 = __ldcs(reinterpret_cast<const float4*>(hmat + row));
        const float4 c4 = __ldcs(reinterpret_cast<const float4*>(cmat + row));
        const float  gv = __ldg(grad + ea);
        const float  pv = __ldg(param + ea);
        const float  mv = __ldg(momentum + ea);
        const float  uv = __ldg(prevu + ea);

        float zf[16];
        #pragma unroll
        for (int g = 0; g < 4; ++g) {
            const float4 bs = wl[16 + g];
            const float bsk[4] = {bs.x, bs.y, bs.z, bs.w};
            #pragma unroll
            for (int k = 0; k < 4; ++k) {
                const float4 w = wl[g * 4 + k];
                float z = bsk[k];
                z = fmaf(w.x, gv, z);
                z = fmaf(w.y, pv, z);
                z = fmaf(w.z, mv, z);
                z = fmaf(w.w, uv, z);
                zf[g * 4 + k] = z;
            }
        }
        const bool hz = (h4.x != 0.0f) || (h4.y != 0.0f) ||
                        (h4.z != 0.0f) || (h4.w != 0.0f);
        if (__any_sync(0xffffffffu, hz))
            add_recurrent(zf, h4, W_hh, colbase);

        float4 hn4, cn4;
        float acc = finish_elem(zf, c4, wup, hn4, cn4);
        if (out_h != nullptr) {
            __stcs(reinterpret_cast<float4*>(out_h + row), hn4);
            __stcs(reinterpret_cast<float4*>(out_c + row), cn4);
        }
        #pragma unroll
        for (int off = 16; off; off >>= 1)
            acc += __shfl_xor_sync(0xffffffffu, acc, off);
        if (lane == 0) {
            const float upd = acc + bup;
            out_upd[ea] = upd;
            if (out_mom != nullptr) out_mom[ea] = fmaf(0.9f, mv, upd);
        }
    }
}

}  // namespace

extern "C" void kernel_launch(void* const* d_in, const int* in_sizes, int n_in,
                              void* d_out, int out_size) {
    const float* param = (const float*)d_in[0];
    const float* grad  = (const float*)d_in[1];
    const float* h     = (const float*)d_in[2];
    const float* c     = (const float*)d_in[3];
    const float* mom   = (const float*)d_in[4];
    const float* prevu = (const float*)d_in[5];
    const float* W_ih  = (const float*)d_in[6];
    const float* W_hh  = (const float*)d_in[7];
    const float* b_ih  = (const float*)d_in[8];
    const float* b_hh  = (const float*)d_in[9];
    const float* W_up  = (const float*)d_in[10];
    const float* b_up  = (const float*)d_in[11];

    const int N = in_sizes[0];
    float* out = (float*)d_out;

    // Output layout: concat(update, h_new, c_new, momentum_new), reference order.
    float* out_upd = out;
    float* out_h   = nullptr;
    float* out_c   = nullptr;
    float* out_mom = nullptr;
    const long long full = 2LL * N + 2LL * N * 128;
    if ((long long)out_size >= full) {
        out_h   = out + N;
        out_c   = out + N + (size_t)N * 128;
        out_mom = out + N + 2 * (size_t)N * 128;
    } else if (out_size >= 2 * N) {
        out_mom = out + N;
    }

    // 1184 = 148 SMs x 8 resident blocks: 32 warps/SM, exactly one full wave.
    const int threads = 128;
    const int blocks  = 1184;
    lstm_opt_kernel<<<blocks, threads>>>(param, grad, h, c, mom, prevu,
                                         W_ih, W_hh, b_ih, b_hh, W_up, b_up,
                                         out_upd, out_h, out_c, out_mom, N);
}